// round 4
// baseline (speedup 1.0000x reference)
#include <cuda_runtime.h>
#include <cuda_bf16.h>
#include <cstdint>
#include <math.h>

#define BATCH 4
#define SEQ   2048
#define DMODEL 1024

// ---------------- device scratch ----------------
__device__ __nv_bfloat16 g_x1[8388608],  g_x2[8388608];    // x planes  [8192][1024]
__device__ __nv_bfloat16 g_wqt1[1048576], g_wqt2[1048576]; // W^T planes [n][k]
__device__ __nv_bfloat16 g_wkt1[1048576], g_wkt2[1048576];
__device__ __nv_bfloat16 g_wvt1[1048576], g_wvt2[1048576];
__device__ __nv_bfloat16 g_q1[8388608],  g_q2[8388608];
__device__ __nv_bfloat16 g_k1[8388608],  g_k2[8388608];
__device__ __nv_bfloat16 g_vt1[8388608], g_vt2[8388608];   // V^T planes [b][1024][2048]
__device__ float         g_s[16777216];                    // scores fp32
__device__ __nv_bfloat16 g_p1[16777216], g_p2[16777216];   // prob planes

// ---------------- helpers ----------------
__device__ __forceinline__ uint32_t smem_u32(const void* p) {
    uint32_t a;
    asm("{ .reg .u64 t; cvta.to.shared.u64 t, %1; cvt.u32.u64 %0, t; }" : "=r"(a) : "l"(p));
    return a;
}
__device__ __forceinline__ void cp_async16(uint32_t d, const void* s) {
    asm volatile("cp.async.cg.shared.global [%0], [%1], 16;" :: "r"(d), "l"(s) : "memory");
}
#define CP_COMMIT() asm volatile("cp.async.commit_group;" ::: "memory")
#define CP_WAIT1()  asm volatile("cp.async.wait_group 1;" ::: "memory")
#define CP_WAIT0()  asm volatile("cp.async.wait_group 0;" ::: "memory")

__device__ __forceinline__ void ldsm4(uint32_t* r, uint32_t a) {
    asm volatile("ldmatrix.sync.aligned.m8n8.x4.shared.b16 {%0,%1,%2,%3}, [%4];"
        : "=r"(r[0]), "=r"(r[1]), "=r"(r[2]), "=r"(r[3]) : "r"(a));
}
__device__ __forceinline__ void mma_bf16(float* c, const uint32_t* a, const uint32_t* b) {
    asm volatile("mma.sync.aligned.m16n8k16.row.col.f32.bf16.bf16.f32 "
        "{%0,%1,%2,%3}, {%4,%5,%6,%7}, {%8,%9}, {%0,%1,%2,%3};"
        : "+f"(c[0]), "+f"(c[1]), "+f"(c[2]), "+f"(c[3])
        : "r"(a[0]), "r"(a[1]), "r"(a[2]), "r"(a[3]), "r"(b[0]), "r"(b[1]));
}
__device__ __forceinline__ void split_pack(float a, float b, uint32_t& hi, uint32_t& lo) {
    __nv_bfloat16 ha = __float2bfloat16(a), hb = __float2bfloat16(b);
    __nv_bfloat16 ra = __float2bfloat16(a - __bfloat162float(ha));
    __nv_bfloat16 rb = __float2bfloat16(b - __bfloat162float(hb));
    __nv_bfloat162 h = __halves2bfloat162(ha, hb);
    __nv_bfloat162 r = __halves2bfloat162(ra, rb);
    hi = *reinterpret_cast<uint32_t*>(&h);
    lo = *reinterpret_cast<uint32_t*>(&r);
}

// ---------------- prep kernels ----------------
__global__ __launch_bounds__(256) void split2_kernel(const float4* __restrict__ X,
                                                     uint2* __restrict__ X1, uint2* __restrict__ X2, int n4) {
    int i = blockIdx.x * 256 + threadIdx.x;
    if (i >= n4) return;
    float4 v = X[i];
    uint2 u1, u2;
    split_pack(v.x, v.y, u1.x, u2.x);
    split_pack(v.z, v.w, u1.y, u2.y);
    X1[i] = u1; X2[i] = u2;
}

// All three weights in one launch: z selects (W, T1, T2)
__global__ __launch_bounds__(256) void wtrans_split3_kernel(
    const float* __restrict__ Wq, const float* __restrict__ Wk, const float* __restrict__ Wv,
    __nv_bfloat16* __restrict__ Tq1, __nv_bfloat16* __restrict__ Tq2,
    __nv_bfloat16* __restrict__ Tk1, __nv_bfloat16* __restrict__ Tk2,
    __nv_bfloat16* __restrict__ Tv1, __nv_bfloat16* __restrict__ Tv2)
{
    const float* W = (blockIdx.z == 0) ? Wq : (blockIdx.z == 1) ? Wk : Wv;
    __nv_bfloat16* T1 = (blockIdx.z == 0) ? Tq1 : (blockIdx.z == 1) ? Tk1 : Tv1;
    __nv_bfloat16* T2 = (blockIdx.z == 0) ? Tq2 : (blockIdx.z == 1) ? Tk2 : Tv2;

    __shared__ float t[32][33];
    int k0 = blockIdx.y * 32, n0 = blockIdx.x * 32;
    int tx = threadIdx.x & 31, ty = threadIdx.x >> 5;
    #pragma unroll
    for (int i = 0; i < 4; i++) {
        int k = ty + i * 8;
        t[k][tx] = W[(long long)(k0 + k) * DMODEL + n0 + tx];
    }
    __syncthreads();
    #pragma unroll
    for (int i = 0; i < 4; i++) {
        int n = ty + i * 8;
        float v = t[tx][n];
        __nv_bfloat16 h = __float2bfloat16(v);
        long long idx = (long long)(n0 + n) * DMODEL + k0 + tx;
        T1[idx] = h;
        T2[idx] = __float2bfloat16(v - __bfloat162float(h));
    }
}

// ---------------- GEMM: C = scale*(A·B^T)(+bias); A[M,K], B[N,K] bf16 2-plane ----------------
// MODE 0: fp32 C row-major. MODE 1: bf16 planes row-major. MODE 2: transposed V^T planes.
#define KC 32
#define TROW 80                      // bytes per smem row (32 bf16 + pad 8)
#define TILE_B (128 * TROW)          // 10240
#define STAGE_B (4 * TILE_B)         // 40960
#define NSTAGE 3
#define DSMEM (NSTAGE * STAGE_B)     // 122880

template<int MODE, bool HAS_BIAS>
__global__ __launch_bounds__(256, 1)
void gemm_mma(const __nv_bfloat16* __restrict__ A1, const __nv_bfloat16* __restrict__ A2, int ldA, long long sA,
              const __nv_bfloat16* __restrict__ B1, const __nv_bfloat16* __restrict__ B2, int ldB, long long sB,
              const float* __restrict__ bias,
              float* __restrict__ C, __nv_bfloat16* __restrict__ C1, __nv_bfloat16* __restrict__ C2,
              int ldC, long long sC, float scale, int K)
{
    extern __shared__ char smem[];
    const uint32_t sbase = smem_u32(smem);

    const int tid = threadIdx.x, lane = tid & 31, wid = tid >> 5;
    const int wm = wid & 3, wn = wid >> 2;
    const long long z = blockIdx.z;
    A1 += z * sA; A2 += z * sA; B1 += z * sB; B2 += z * sB;
    if (MODE == 0) C += z * sC;
    const int m0 = blockIdx.y * 128, n0 = blockIdx.x * 128;

    auto load_stage = [&](int stg, int k0) {
        const uint32_t st = sbase + stg * STAGE_B;
        #pragma unroll
        for (int j = 0; j < 2; j++) {
            int cc = tid + j * 256;        // 0..511
            int row = cc >> 2, seg = cc & 3;
            uint32_t so = row * TROW + seg * 16;
            cp_async16(st + 0 * TILE_B + so, A1 + (long long)(m0 + row) * ldA + k0 + seg * 8);
            cp_async16(st + 1 * TILE_B + so, A2 + (long long)(m0 + row) * ldA + k0 + seg * 8);
            cp_async16(st + 2 * TILE_B + so, B1 + (long long)(n0 + row) * ldB + k0 + seg * 8);
            cp_async16(st + 3 * TILE_B + so, B2 + (long long)(n0 + row) * ldB + k0 + seg * 8);
        }
    };

    float acc[2][8][4] = {};

    const int CH = K / KC;
    load_stage(0, 0);  CP_COMMIT();
    load_stage(1, KC); CP_COMMIT();

    int stage = 0;
    for (int c = 0; c < CH; c++) {
        if (c + 1 < CH) CP_WAIT1(); else CP_WAIT0();
        __syncthreads();
        // prefetch 2 chunks ahead into the ring (disjoint from compute stage & stage c+1)
        if (c + 2 < CH) {
            int ps = stage + 2; if (ps >= NSTAGE) ps -= NSTAGE;
            load_stage(ps, (c + 2) * KC);
            CP_COMMIT();
        }
        const uint32_t st = sbase + stage * STAGE_B;

        #pragma unroll
        for (int ks = 0; ks < 2; ks++) {
            const uint32_t coff = (ks * 16 + ((lane >> 4) << 3)) * 2;
            uint32_t a[2][2][4];
            #pragma unroll
            for (int mt = 0; mt < 2; mt++)
                #pragma unroll
                for (int p = 0; p < 2; p++) {
                    uint32_t addr = st + p * TILE_B
                                  + (wm * 32 + mt * 16 + (lane & 15)) * TROW + coff;
                    ldsm4(a[mt][p], addr);
                }
            uint32_t b[8][2][2];
            #pragma unroll
            for (int nt2 = 0; nt2 < 4; nt2++)
                #pragma unroll
                for (int p = 0; p < 2; p++) {
                    uint32_t r[4];
                    uint32_t addr = st + (2 + p) * TILE_B
                                  + (wn * 64 + nt2 * 16 + (lane & 15)) * TROW + coff;
                    ldsm4(r, addr);
                    b[nt2 * 2 + 0][p][0] = r[0]; b[nt2 * 2 + 0][p][1] = r[2];
                    b[nt2 * 2 + 1][p][0] = r[1]; b[nt2 * 2 + 1][p][1] = r[3];
                }
            #pragma unroll
            for (int mt = 0; mt < 2; mt++)
                #pragma unroll
                for (int nt = 0; nt < 8; nt++) {
                    mma_bf16(acc[mt][nt], a[mt][0], b[nt][0]);   // hi*hi
                    mma_bf16(acc[mt][nt], a[mt][0], b[nt][1]);   // hi*lo
                    mma_bf16(acc[mt][nt], a[mt][1], b[nt][0]);   // lo*hi
                }
        }
        if (++stage == NSTAGE) stage = 0;
    }
    __syncthreads();

    // ---------------- epilogue ----------------
    if (MODE == 2) {
        float* stg = (float*)smem;     // [128][133]
        #pragma unroll
        for (int mt = 0; mt < 2; mt++)
            #pragma unroll
            for (int h = 0; h < 2; h++) {
                int m = wm * 32 + mt * 16 + (lane >> 2) + h * 8;
                #pragma unroll
                for (int nt = 0; nt < 8; nt++) {
                    int n = wn * 64 + nt * 8 + ((lane & 3) << 1);
                    float v0 = acc[mt][nt][h * 2 + 0] * scale;
                    float v1 = acc[mt][nt][h * 2 + 1] * scale;
                    if (HAS_BIAS) { v0 += __ldg(bias + n0 + n); v1 += __ldg(bias + n0 + n + 1); }
                    stg[m * 133 + n] = v0;
                    stg[m * 133 + n + 1] = v1;
                }
            }
        __syncthreads();
        #pragma unroll 4
        for (int i = 0; i < 64; i++) {
            int linear = i * 256 + tid;       // 0..16383
            int n = linear >> 7, m = linear & 127;
            float v = stg[m * 133 + n];
            int gm = m0 + m;
            long long idx = ((long long)(gm >> 11) * DMODEL + (n0 + n)) * SEQ + (gm & (SEQ - 1));
            __nv_bfloat16 hh = __float2bfloat16(v);
            C1[idx] = hh;
            C2[idx] = __float2bfloat16(v - __bfloat162float(hh));
        }
    } else {
        #pragma unroll
        for (int mt = 0; mt < 2; mt++)
            #pragma unroll
            for (int h = 0; h < 2; h++) {
                int m = m0 + wm * 32 + mt * 16 + (lane >> 2) + h * 8;
                #pragma unroll
                for (int nt = 0; nt < 8; nt++) {
                    int n = n0 + wn * 64 + nt * 8 + ((lane & 3) << 1);
                    float v0 = acc[mt][nt][h * 2 + 0] * scale;
                    float v1 = acc[mt][nt][h * 2 + 1] * scale;
                    if (HAS_BIAS) { v0 += __ldg(bias + n); v1 += __ldg(bias + n + 1); }
                    if (MODE == 0) {
                        float2 f; f.x = v0; f.y = v1;
                        *(float2*)(C + (long long)m * ldC + n) = f;
                    } else {
                        uint32_t u1, u2;
                        split_pack(v0, v1, u1, u2);
                        *(uint32_t*)(C1 + (long long)m * ldC + n) = u1;
                        *(uint32_t*)(C2 + (long long)m * ldC + n) = u2;
                    }
                }
            }
    }
}

// ---------------- softmax: fp32 scores -> bf16 prob planes ----------------
__global__ __launch_bounds__(256) void softmax_planes_kernel(const float* __restrict__ S,
                                                             __nv_bfloat16* __restrict__ P1,
                                                             __nv_bfloat16* __restrict__ P2) {
    const long long row = blockIdx.x;
    const float* p = S + row * SEQ;
    const int tid = threadIdx.x, lane = tid & 31, w = tid >> 5;
    __shared__ float red[8];

    float vals[8];
    const float4 a = *(const float4*)(p + tid * 8);
    const float4 b = *(const float4*)(p + tid * 8 + 4);
    vals[0]=a.x; vals[1]=a.y; vals[2]=a.z; vals[3]=a.w;
    vals[4]=b.x; vals[5]=b.y; vals[6]=b.z; vals[7]=b.w;

    float m = -INFINITY;
    #pragma unroll
    for (int i = 0; i < 8; i++) m = fmaxf(m, vals[i]);
    #pragma unroll
    for (int o = 16; o; o >>= 1) m = fmaxf(m, __shfl_xor_sync(0xffffffffu, m, o));
    if (lane == 0) red[w] = m;
    __syncthreads();
    if (w == 0) {
        float x = red[lane & 7];
        #pragma unroll
        for (int o = 4; o; o >>= 1) x = fmaxf(x, __shfl_xor_sync(0xffffffffu, x, o));
        if (lane == 0) red[0] = x;
    }
    __syncthreads();
    m = red[0];
    __syncthreads();

    float s = 0.0f;
    #pragma unroll
    for (int i = 0; i < 8; i++) { vals[i] = __expf(vals[i] - m); s += vals[i]; }
    #pragma unroll
    for (int o = 16; o; o >>= 1) s += __shfl_xor_sync(0xffffffffu, s, o);
    if (lane == 0) red[w] = s;
    __syncthreads();
    if (w == 0) {
        float x = red[lane & 7];
        #pragma unroll
        for (int o = 4; o; o >>= 1) x += __shfl_xor_sync(0xffffffffu, x, o);
        if (lane == 0) red[0] = x;
    }
    __syncthreads();
    const float inv = 1.0f / red[0];

    uint4 u1, u2;
    split_pack(vals[0]*inv, vals[1]*inv, u1.x, u2.x);
    split_pack(vals[2]*inv, vals[3]*inv, u1.y, u2.y);
    split_pack(vals[4]*inv, vals[5]*inv, u1.z, u2.z);
    split_pack(vals[6]*inv, vals[7]*inv, u1.w, u2.w);
    *(uint4*)(P1 + row * SEQ + tid * 8) = u1;
    *(uint4*)(P2 + row * SEQ + tid * 8) = u2;
}

// ---------------- launch ----------------
extern "C" void kernel_launch(void* const* d_in, const int* in_sizes, int n_in,
                              void* d_out, int out_size)
{
    const float* x  = (const float*)d_in[0];
    const float* Wq = (const float*)d_in[1];
    const float* bq = (const float*)d_in[2];
    const float* Wk = (const float*)d_in[3];
    const float* bk = (const float*)d_in[4];
    const float* Wv = (const float*)d_in[5];
    const float* bv = (const float*)d_in[6];
    float* out = (float*)d_out;

    void *x1, *x2, *wqt1, *wqt2, *wkt1, *wkt2, *wvt1, *wvt2;
    void *q1, *q2, *k1, *k2, *vt1, *vt2, *s, *p1, *p2;
    cudaGetSymbolAddress(&x1, g_x1);   cudaGetSymbolAddress(&x2, g_x2);
    cudaGetSymbolAddress(&wqt1, g_wqt1); cudaGetSymbolAddress(&wqt2, g_wqt2);
    cudaGetSymbolAddress(&wkt1, g_wkt1); cudaGetSymbolAddress(&wkt2, g_wkt2);
    cudaGetSymbolAddress(&wvt1, g_wvt1); cudaGetSymbolAddress(&wvt2, g_wvt2);
    cudaGetSymbolAddress(&q1, g_q1);   cudaGetSymbolAddress(&q2, g_q2);
    cudaGetSymbolAddress(&k1, g_k1);   cudaGetSymbolAddress(&k2, g_k2);
    cudaGetSymbolAddress(&vt1, g_vt1); cudaGetSymbolAddress(&vt2, g_vt2);
    cudaGetSymbolAddress(&s, g_s);
    cudaGetSymbolAddress(&p1, g_p1);   cudaGetSymbolAddress(&p2, g_p2);

    cudaFuncSetAttribute(gemm_mma<0, false>, cudaFuncAttributeMaxDynamicSharedMemorySize, DSMEM);
    cudaFuncSetAttribute(gemm_mma<1, true >, cudaFuncAttributeMaxDynamicSharedMemorySize, DSMEM);
    cudaFuncSetAttribute(gemm_mma<2, true >, cudaFuncAttributeMaxDynamicSharedMemorySize, DSMEM);

    const int MQ = BATCH * SEQ; // 8192

    // launch 0
    split2_kernel<<<MQ * DMODEL / 4 / 256, 256>>>((const float4*)x, (uint2*)x1, (uint2*)x2, MQ * DMODEL / 4);

    // launch 1 (all three weight transposes fused)
    dim3 gw(DMODEL / 32, DMODEL / 32, 3);
    wtrans_split3_kernel<<<gw, 256>>>(Wq, Wk, Wv,
                                      (__nv_bfloat16*)wqt1, (__nv_bfloat16*)wqt2,
                                      (__nv_bfloat16*)wkt1, (__nv_bfloat16*)wkt2,
                                      (__nv_bfloat16*)wvt1, (__nv_bfloat16*)wvt2);

    // launches 2-4
    dim3 gp(DMODEL / 128, MQ / 128, 1);
    gemm_mma<1, true><<<gp, 256, DSMEM>>>((__nv_bfloat16*)x1, (__nv_bfloat16*)x2, DMODEL, 0,
                                          (__nv_bfloat16*)wqt1, (__nv_bfloat16*)wqt2, DMODEL, 0,
                                          bq, nullptr, (__nv_bfloat16*)q1, (__nv_bfloat16*)q2,
                                          DMODEL, 0, 1.0f, DMODEL);
    gemm_mma<1, true><<<gp, 256, DSMEM>>>((__nv_bfloat16*)x1, (__nv_bfloat16*)x2, DMODEL, 0,
                                          (__nv_bfloat16*)wkt1, (__nv_bfloat16*)wkt2, DMODEL, 0,
                                          bk, nullptr, (__nv_bfloat16*)k1, (__nv_bfloat16*)k2,
                                          DMODEL, 0, 1.0f, DMODEL);
    gemm_mma<2, true><<<gp, 256, DSMEM>>>((__nv_bfloat16*)x1, (__nv_bfloat16*)x2, DMODEL, 0,
                                          (__nv_bfloat16*)wvt1, (__nv_bfloat16*)wvt2, DMODEL, 0,
                                          bv, nullptr, (__nv_bfloat16*)vt1, (__nv_bfloat16*)vt2,
                                          0, 0, 1.0f, DMODEL);

    // launch 5 (ncu -s 5 -c 1 profiles this: the scores GEMM)
    dim3 gs(SEQ / 128, SEQ / 128, BATCH);
    gemm_mma<0, false><<<gs, 256, DSMEM>>>((__nv_bfloat16*)q1, (__nv_bfloat16*)q2, DMODEL, (long long)SEQ * DMODEL,
                                           (__nv_bfloat16*)k1, (__nv_bfloat16*)k2, DMODEL, (long long)SEQ * DMODEL,
                                           nullptr, (float*)s, nullptr, nullptr,
                                           SEQ, (long long)SEQ * SEQ, 0.03125f, DMODEL);

    softmax_planes_kernel<<<BATCH * SEQ, 256>>>((const float*)s, (__nv_bfloat16*)p1, (__nv_bfloat16*)p2);

    dim3 go(DMODEL / 128, SEQ / 128, BATCH);
    gemm_mma<0, false><<<go, 256, DSMEM>>>((__nv_bfloat16*)p1, (__nv_bfloat16*)p2, SEQ, (long long)SEQ * SEQ,
                                           (__nv_bfloat16*)vt1, (__nv_bfloat16*)vt2, SEQ, (long long)DMODEL * SEQ,
                                           nullptr, out, nullptr, nullptr,
                                           DMODEL, (long long)SEQ * DMODEL, 1.0f, SEQ);
}

// round 5
// speedup vs baseline: 1.1365x; 1.1365x over previous
#include <cuda_runtime.h>
#include <cuda_bf16.h>
#include <cstdint>
#include <math.h>

#define BATCH 4
#define SEQ   2048
#define DMODEL 1024

// ---------------- device scratch ----------------
__device__ __nv_bfloat16 g_x1[8388608],  g_x2[8388608];    // x planes  [8192][1024]
__device__ __nv_bfloat16 g_wqt1[1048576], g_wqt2[1048576]; // W^T planes [n][k]
__device__ __nv_bfloat16 g_wkt1[1048576], g_wkt2[1048576];
__device__ __nv_bfloat16 g_wvt1[1048576], g_wvt2[1048576];
__device__ __nv_bfloat16 g_q1[8388608],  g_q2[8388608];
__device__ __nv_bfloat16 g_k1[8388608],  g_k2[8388608];
__device__ __nv_bfloat16 g_vt1[8388608], g_vt2[8388608];   // V^T planes [b][1024][2048]
__device__ float         g_s[16777216];                    // scores fp32
__device__ __nv_bfloat16 g_p1[16777216], g_p2[16777216];   // prob planes

// ---------------- helpers ----------------
__device__ __forceinline__ uint32_t smem_u32(const void* p) {
    uint32_t a;
    asm("{ .reg .u64 t; cvta.to.shared.u64 t, %1; cvt.u32.u64 %0, t; }" : "=r"(a) : "l"(p));
    return a;
}
__device__ __forceinline__ void cp_async16(uint32_t d, const void* s) {
    asm volatile("cp.async.cg.shared.global [%0], [%1], 16;" :: "r"(d), "l"(s) : "memory");
}
#define CP_COMMIT() asm volatile("cp.async.commit_group;" ::: "memory")
#define CP_WAIT1()  asm volatile("cp.async.wait_group 1;" ::: "memory")
#define CP_WAIT0()  asm volatile("cp.async.wait_group 0;" ::: "memory")

__device__ __forceinline__ void ldsm4(uint32_t* r, uint32_t a) {
    asm volatile("ldmatrix.sync.aligned.m8n8.x4.shared.b16 {%0,%1,%2,%3}, [%4];"
        : "=r"(r[0]), "=r"(r[1]), "=r"(r[2]), "=r"(r[3]) : "r"(a));
}
__device__ __forceinline__ void mma_bf16(float* c, const uint32_t* a, const uint32_t* b) {
    asm volatile("mma.sync.aligned.m16n8k16.row.col.f32.bf16.bf16.f32 "
        "{%0,%1,%2,%3}, {%4,%5,%6,%7}, {%8,%9}, {%0,%1,%2,%3};"
        : "+f"(c[0]), "+f"(c[1]), "+f"(c[2]), "+f"(c[3])
        : "r"(a[0]), "r"(a[1]), "r"(a[2]), "r"(a[3]), "r"(b[0]), "r"(b[1]));
}
__device__ __forceinline__ void split_pack(float a, float b, uint32_t& hi, uint32_t& lo) {
    __nv_bfloat16 ha = __float2bfloat16(a), hb = __float2bfloat16(b);
    __nv_bfloat16 ra = __float2bfloat16(a - __bfloat162float(ha));
    __nv_bfloat16 rb = __float2bfloat16(b - __bfloat162float(hb));
    __nv_bfloat162 h = __halves2bfloat162(ha, hb);
    __nv_bfloat162 r = __halves2bfloat162(ra, rb);
    hi = *reinterpret_cast<uint32_t*>(&h);
    lo = *reinterpret_cast<uint32_t*>(&r);
}

// ---------------- prep kernels ----------------
__global__ __launch_bounds__(256) void split2_kernel(const float4* __restrict__ X,
                                                     uint2* __restrict__ X1, uint2* __restrict__ X2, int n4) {
    int i = blockIdx.x * 256 + threadIdx.x;
    if (i >= n4) return;
    float4 v = X[i];
    uint2 u1, u2;
    split_pack(v.x, v.y, u1.x, u2.x);
    split_pack(v.z, v.w, u1.y, u2.y);
    X1[i] = u1; X2[i] = u2;
}

__global__ __launch_bounds__(256) void wtrans_split3_kernel(
    const float* __restrict__ Wq, const float* __restrict__ Wk, const float* __restrict__ Wv,
    __nv_bfloat16* __restrict__ Tq1, __nv_bfloat16* __restrict__ Tq2,
    __nv_bfloat16* __restrict__ Tk1, __nv_bfloat16* __restrict__ Tk2,
    __nv_bfloat16* __restrict__ Tv1, __nv_bfloat16* __restrict__ Tv2)
{
    const float* W = (blockIdx.z == 0) ? Wq : (blockIdx.z == 1) ? Wk : Wv;
    __nv_bfloat16* T1 = (blockIdx.z == 0) ? Tq1 : (blockIdx.z == 1) ? Tk1 : Tv1;
    __nv_bfloat16* T2 = (blockIdx.z == 0) ? Tq2 : (blockIdx.z == 1) ? Tk2 : Tv2;

    __shared__ float t[32][33];
    int k0 = blockIdx.y * 32, n0 = blockIdx.x * 32;
    int tx = threadIdx.x & 31, ty = threadIdx.x >> 5;
    #pragma unroll
    for (int i = 0; i < 4; i++) {
        int k = ty + i * 8;
        t[k][tx] = W[(long long)(k0 + k) * DMODEL + n0 + tx];
    }
    __syncthreads();
    #pragma unroll
    for (int i = 0; i < 4; i++) {
        int n = ty + i * 8;
        float v = t[tx][n];
        __nv_bfloat16 h = __float2bfloat16(v);
        long long idx = (long long)(n0 + n) * DMODEL + k0 + tx;
        T1[idx] = h;
        T2[idx] = __float2bfloat16(v - __bfloat162float(h));
    }
}

// ---------------- GEMM: C = scale*(A·B^T)(+bias); A[M,K], B[N,K] bf16 2-plane ----------------
#define KC 32
#define TROW 80                      // bytes per smem row (32 bf16 + pad 8)
#define TILE_B (128 * TROW)          // 10240
#define STAGE_B (4 * TILE_B)         // 40960
#define DSMEM (2 * STAGE_B)          // 81920

template<int MODE, bool HAS_BIAS>
__global__ __launch_bounds__(256, 2)
void gemm_mma(const __nv_bfloat16* __restrict__ A1, const __nv_bfloat16* __restrict__ A2, int ldA, long long sA,
              const __nv_bfloat16* __restrict__ B1, const __nv_bfloat16* __restrict__ B2, int ldB, long long sB,
              const float* __restrict__ bias,
              float* __restrict__ C, __nv_bfloat16* __restrict__ C1, __nv_bfloat16* __restrict__ C2,
              int ldC, long long sC, float scale, int K)
{
    extern __shared__ char smem[];
    const uint32_t sbase = smem_u32(smem);

    const int tid = threadIdx.x, lane = tid & 31, wid = tid >> 5;
    const int wm = wid & 3, wn = wid >> 2;
    const long long z = blockIdx.z;
    A1 += z * sA; A2 += z * sA; B1 += z * sB; B2 += z * sB;
    if (MODE == 0) C += z * sC;
    const int m0 = blockIdx.y * 128, n0 = blockIdx.x * 128;

    auto load_stage = [&](int stg, int k0) {
        const uint32_t st = sbase + stg * STAGE_B;
        #pragma unroll
        for (int j = 0; j < 2; j++) {
            int cc = tid + j * 256;        // 0..511
            int row = cc >> 2, seg = cc & 3;
            uint32_t so = row * TROW + seg * 16;
            cp_async16(st + 0 * TILE_B + so, A1 + (long long)(m0 + row) * ldA + k0 + seg * 8);
            cp_async16(st + 1 * TILE_B + so, A2 + (long long)(m0 + row) * ldA + k0 + seg * 8);
            cp_async16(st + 2 * TILE_B + so, B1 + (long long)(n0 + row) * ldB + k0 + seg * 8);
            cp_async16(st + 3 * TILE_B + so, B2 + (long long)(n0 + row) * ldB + k0 + seg * 8);
        }
    };

    float acc[2][8][4] = {};

    const int CH = K / KC;
    load_stage(0, 0);  CP_COMMIT();
    load_stage(1, KC); CP_COMMIT();

    for (int c = 0; c < CH; c++) {
        if (c + 1 < CH) CP_WAIT1(); else CP_WAIT0();
        __syncthreads();
        const uint32_t st = sbase + (c & 1) * STAGE_B;

        #pragma unroll
        for (int ks = 0; ks < 2; ks++) {
            const uint32_t coff = (ks * 16 + ((lane >> 4) << 3)) * 2;
            const uint32_t arow = (wm * 32 + (lane & 15)) * TROW + coff;
            const uint32_t brow = (wn * 64 + (lane & 15)) * TROW + coff;

            // A fragments, both planes
            uint32_t a0[2][4], a1[2][4];
            #pragma unroll
            for (int mt = 0; mt < 2; mt++) {
                ldsm4(a0[mt], st + 0 * TILE_B + arow + mt * 16 * TROW);
                ldsm4(a1[mt], st + 1 * TILE_B + arow + mt * 16 * TROW);
            }
            // B plane 0
            uint32_t b0[8][2];
            #pragma unroll
            for (int nt2 = 0; nt2 < 4; nt2++) {
                uint32_t r[4];
                ldsm4(r, st + 2 * TILE_B + brow + nt2 * 16 * TROW);
                b0[nt2 * 2 + 0][0] = r[0]; b0[nt2 * 2 + 0][1] = r[2];
                b0[nt2 * 2 + 1][0] = r[1]; b0[nt2 * 2 + 1][1] = r[3];
            }
            // pass 0: a0 * b0  (16 independent accumulators)
            #pragma unroll
            for (int mt = 0; mt < 2; mt++)
                #pragma unroll
                for (int nt = 0; nt < 8; nt++)
                    mma_bf16(acc[mt][nt], a0[mt], b0[nt]);
            // B plane 1 (latency hidden under pass 1)
            uint32_t b1[8][2];
            #pragma unroll
            for (int nt2 = 0; nt2 < 4; nt2++) {
                uint32_t r[4];
                ldsm4(r, st + 3 * TILE_B + brow + nt2 * 16 * TROW);
                b1[nt2 * 2 + 0][0] = r[0]; b1[nt2 * 2 + 0][1] = r[2];
                b1[nt2 * 2 + 1][0] = r[1]; b1[nt2 * 2 + 1][1] = r[3];
            }
            // pass 1: a1 * b0
            #pragma unroll
            for (int mt = 0; mt < 2; mt++)
                #pragma unroll
                for (int nt = 0; nt < 8; nt++)
                    mma_bf16(acc[mt][nt], a1[mt], b0[nt]);
            // pass 2: a0 * b1
            #pragma unroll
            for (int mt = 0; mt < 2; mt++)
                #pragma unroll
                for (int nt = 0; nt < 8; nt++)
                    mma_bf16(acc[mt][nt], a0[mt], b1[nt]);
        }
        __syncthreads();
        if (c + 2 < CH) load_stage(c & 1, (c + 2) * KC);
        CP_COMMIT();
    }
    __syncthreads();

    // ---------------- epilogue ----------------
    if (MODE == 2) {
        float* stg = (float*)smem;     // [128][133]
        #pragma unroll
        for (int mt = 0; mt < 2; mt++)
            #pragma unroll
            for (int h = 0; h < 2; h++) {
                int m = wm * 32 + mt * 16 + (lane >> 2) + h * 8;
                #pragma unroll
                for (int nt = 0; nt < 8; nt++) {
                    int n = wn * 64 + nt * 8 + ((lane & 3) << 1);
                    float v0 = acc[mt][nt][h * 2 + 0] * scale;
                    float v1 = acc[mt][nt][h * 2 + 1] * scale;
                    if (HAS_BIAS) { v0 += __ldg(bias + n0 + n); v1 += __ldg(bias + n0 + n + 1); }
                    stg[m * 133 + n] = v0;
                    stg[m * 133 + n + 1] = v1;
                }
            }
        __syncthreads();
        #pragma unroll 4
        for (int i = 0; i < 64; i++) {
            int linear = i * 256 + tid;       // 0..16383
            int n = linear >> 7, m = linear & 127;
            float v = stg[m * 133 + n];
            int gm = m0 + m;
            long long idx = ((long long)(gm >> 11) * DMODEL + (n0 + n)) * SEQ + (gm & (SEQ - 1));
            __nv_bfloat16 hh = __float2bfloat16(v);
            C1[idx] = hh;
            C2[idx] = __float2bfloat16(v - __bfloat162float(hh));
        }
    } else {
        #pragma unroll
        for (int mt = 0; mt < 2; mt++)
            #pragma unroll
            for (int h = 0; h < 2; h++) {
                int m = m0 + wm * 32 + mt * 16 + (lane >> 2) + h * 8;
                #pragma unroll
                for (int nt = 0; nt < 8; nt++) {
                    int n = n0 + wn * 64 + nt * 8 + ((lane & 3) << 1);
                    float v0 = acc[mt][nt][h * 2 + 0] * scale;
                    float v1 = acc[mt][nt][h * 2 + 1] * scale;
                    if (HAS_BIAS) { v0 += __ldg(bias + n); v1 += __ldg(bias + n + 1); }
                    if (MODE == 0) {
                        float2 f; f.x = v0; f.y = v1;
                        *(float2*)(C + (long long)m * ldC + n) = f;
                    } else {
                        uint32_t u1, u2;
                        split_pack(v0, v1, u1, u2);
                        *(uint32_t*)(C1 + (long long)m * ldC + n) = u1;
                        *(uint32_t*)(C2 + (long long)m * ldC + n) = u2;
                    }
                }
            }
    }
}

// ---------------- softmax: fp32 scores -> bf16 prob planes ----------------
__global__ __launch_bounds__(256) void softmax_planes_kernel(const float* __restrict__ S,
                                                             __nv_bfloat16* __restrict__ P1,
                                                             __nv_bfloat16* __restrict__ P2) {
    const long long row = blockIdx.x;
    const float* p = S + row * SEQ;
    const int tid = threadIdx.x, lane = tid & 31, w = tid >> 5;
    __shared__ float red[8];

    float vals[8];
    const float4 a = *(const float4*)(p + tid * 8);
    const float4 b = *(const float4*)(p + tid * 8 + 4);
    vals[0]=a.x; vals[1]=a.y; vals[2]=a.z; vals[3]=a.w;
    vals[4]=b.x; vals[5]=b.y; vals[6]=b.z; vals[7]=b.w;

    float m = -INFINITY;
    #pragma unroll
    for (int i = 0; i < 8; i++) m = fmaxf(m, vals[i]);
    #pragma unroll
    for (int o = 16; o; o >>= 1) m = fmaxf(m, __shfl_xor_sync(0xffffffffu, m, o));
    if (lane == 0) red[w] = m;
    __syncthreads();
    if (w == 0) {
        float x = red[lane & 7];
        #pragma unroll
        for (int o = 4; o; o >>= 1) x = fmaxf(x, __shfl_xor_sync(0xffffffffu, x, o));
        if (lane == 0) red[0] = x;
    }
    __syncthreads();
    m = red[0];
    __syncthreads();

    float s = 0.0f;
    #pragma unroll
    for (int i = 0; i < 8; i++) { vals[i] = __expf(vals[i] - m); s += vals[i]; }
    #pragma unroll
    for (int o = 16; o; o >>= 1) s += __shfl_xor_sync(0xffffffffu, s, o);
    if (lane == 0) red[w] = s;
    __syncthreads();
    if (w == 0) {
        float x = red[lane & 7];
        #pragma unroll
        for (int o = 4; o; o >>= 1) x += __shfl_xor_sync(0xffffffffu, x, o);
        if (lane == 0) red[0] = x;
    }
    __syncthreads();
    const float inv = 1.0f / red[0];

    uint4 u1, u2;
    split_pack(vals[0]*inv, vals[1]*inv, u1.x, u2.x);
    split_pack(vals[2]*inv, vals[3]*inv, u1.y, u2.y);
    split_pack(vals[4]*inv, vals[5]*inv, u1.z, u2.z);
    split_pack(vals[6]*inv, vals[7]*inv, u1.w, u2.w);
    *(uint4*)(P1 + row * SEQ + tid * 8) = u1;
    *(uint4*)(P2 + row * SEQ + tid * 8) = u2;
}

// ---------------- launch ----------------
extern "C" void kernel_launch(void* const* d_in, const int* in_sizes, int n_in,
                              void* d_out, int out_size)
{
    const float* x  = (const float*)d_in[0];
    const float* Wq = (const float*)d_in[1];
    const float* bq = (const float*)d_in[2];
    const float* Wk = (const float*)d_in[3];
    const float* bk = (const float*)d_in[4];
    const float* Wv = (const float*)d_in[5];
    const float* bv = (const float*)d_in[6];
    float* out = (float*)d_out;

    void *x1, *x2, *wqt1, *wqt2, *wkt1, *wkt2, *wvt1, *wvt2;
    void *q1, *q2, *k1, *k2, *vt1, *vt2, *s, *p1, *p2;
    cudaGetSymbolAddress(&x1, g_x1);   cudaGetSymbolAddress(&x2, g_x2);
    cudaGetSymbolAddress(&wqt1, g_wqt1); cudaGetSymbolAddress(&wqt2, g_wqt2);
    cudaGetSymbolAddress(&wkt1, g_wkt1); cudaGetSymbolAddress(&wkt2, g_wkt2);
    cudaGetSymbolAddress(&wvt1, g_wvt1); cudaGetSymbolAddress(&wvt2, g_wvt2);
    cudaGetSymbolAddress(&q1, g_q1);   cudaGetSymbolAddress(&q2, g_q2);
    cudaGetSymbolAddress(&k1, g_k1);   cudaGetSymbolAddress(&k2, g_k2);
    cudaGetSymbolAddress(&vt1, g_vt1); cudaGetSymbolAddress(&vt2, g_vt2);
    cudaGetSymbolAddress(&s, g_s);
    cudaGetSymbolAddress(&p1, g_p1);   cudaGetSymbolAddress(&p2, g_p2);

    cudaFuncSetAttribute(gemm_mma<0, false>, cudaFuncAttributeMaxDynamicSharedMemorySize, DSMEM);
    cudaFuncSetAttribute(gemm_mma<1, true >, cudaFuncAttributeMaxDynamicSharedMemorySize, DSMEM);
    cudaFuncSetAttribute(gemm_mma<2, true >, cudaFuncAttributeMaxDynamicSharedMemorySize, DSMEM);

    const int MQ = BATCH * SEQ; // 8192

    // launch 0
    split2_kernel<<<MQ * DMODEL / 4 / 256, 256>>>((const float4*)x, (uint2*)x1, (uint2*)x2, MQ * DMODEL / 4);

    // launch 1
    dim3 gw(DMODEL / 32, DMODEL / 32, 3);
    wtrans_split3_kernel<<<gw, 256>>>(Wq, Wk, Wv,
                                      (__nv_bfloat16*)wqt1, (__nv_bfloat16*)wqt2,
                                      (__nv_bfloat16*)wkt1, (__nv_bfloat16*)wkt2,
                                      (__nv_bfloat16*)wvt1, (__nv_bfloat16*)wvt2);

    // launches 2-4
    dim3 gp(DMODEL / 128, MQ / 128, 1);
    gemm_mma<1, true><<<gp, 256, DSMEM>>>((__nv_bfloat16*)x1, (__nv_bfloat16*)x2, DMODEL, 0,
                                          (__nv_bfloat16*)wqt1, (__nv_bfloat16*)wqt2, DMODEL, 0,
                                          bq, nullptr, (__nv_bfloat16*)q1, (__nv_bfloat16*)q2,
                                          DMODEL, 0, 1.0f, DMODEL);
    gemm_mma<1, true><<<gp, 256, DSMEM>>>((__nv_bfloat16*)x1, (__nv_bfloat16*)x2, DMODEL, 0,
                                          (__nv_bfloat16*)wkt1, (__nv_bfloat16*)wkt2, DMODEL, 0,
                                          bk, nullptr, (__nv_bfloat16*)k1, (__nv_bfloat16*)k2,
                                          DMODEL, 0, 1.0f, DMODEL);
    gemm_mma<2, true><<<gp, 256, DSMEM>>>((__nv_bfloat16*)x1, (__nv_bfloat16*)x2, DMODEL, 0,
                                          (__nv_bfloat16*)wvt1, (__nv_bfloat16*)wvt2, DMODEL, 0,
                                          bv, nullptr, (__nv_bfloat16*)vt1, (__nv_bfloat16*)vt2,
                                          0, 0, 1.0f, DMODEL);

    // launch 5 (ncu -s 5 -c 1 profiles this: the scores GEMM)
    dim3 gs(SEQ / 128, SEQ / 128, BATCH);
    gemm_mma<0, false><<<gs, 256, DSMEM>>>((__nv_bfloat16*)q1, (__nv_bfloat16*)q2, DMODEL, (long long)SEQ * DMODEL,
                                           (__nv_bfloat16*)k1, (__nv_bfloat16*)k2, DMODEL, (long long)SEQ * DMODEL,
                                           nullptr, (float*)s, nullptr, nullptr,
                                           SEQ, (long long)SEQ * SEQ, 0.03125f, DMODEL);

    softmax_planes_kernel<<<BATCH * SEQ, 256>>>((const float*)s, (__nv_bfloat16*)p1, (__nv_bfloat16*)p2);

    dim3 go(DMODEL / 128, SEQ / 128, BATCH);
    gemm_mma<0, false><<<go, 256, DSMEM>>>((__nv_bfloat16*)p1, (__nv_bfloat16*)p2, SEQ, (long long)SEQ * SEQ,
                                           (__nv_bfloat16*)vt1, (__nv_bfloat16*)vt2, SEQ, (long long)DMODEL * SEQ,
                                           nullptr, out, nullptr, nullptr,
                                           DMODEL, (long long)SEQ * DMODEL, 1.0f, SEQ);
}